// round 1
// baseline (speedup 1.0000x reference)
#include <cuda_runtime.h>
#include <math.h>

#define BB 4
#define NN 4096
#define DD 256
#define MTOT (BB*NN)   // 16384

// Scratch (static device allocations are the sanctioned mechanism)
__device__ float g_Q[MTOT*DD];
__device__ float g_K[MTOT*DD];
__device__ float g_V[MTOT*DD];
__device__ float g_att[MTOT*DD];

// ---------------------------------------------------------------------------
// GEMM: C[M,256] = A[M,256] @ W[256,256] (+ optional bias), 64x64 tile,
// 256 threads, 4x4 register tile per thread, BK=16.
// ---------------------------------------------------------------------------
template<bool ADD_BIAS>
__global__ __launch_bounds__(256) void gemm256(const float* __restrict__ A,
                                               const float* __restrict__ W,
                                               const float* __restrict__ bias,
                                               float* __restrict__ C)
{
    __shared__ float As[64][17];   // padded to avoid bank conflicts
    __shared__ float Ws[16][64];

    const int t  = threadIdx.x;
    const int tx = t & 15;
    const int ty = t >> 4;
    const int m0 = blockIdx.x * 64;
    const int n0 = blockIdx.y * 64;

    const int lr = t >> 2;          // As load row (0..63)
    const int lc = (t & 3) * 4;     // As load col (0,4,8,12)

    float acc[4][4] = {};

    for (int kk = 0; kk < 256; kk += 16) {
        float4 av = *(const float4*)(A + (size_t)(m0 + lr) * 256 + kk + lc);
        As[lr][lc + 0] = av.x; As[lr][lc + 1] = av.y;
        As[lr][lc + 2] = av.z; As[lr][lc + 3] = av.w;
        float4 wv = *(const float4*)(W + (size_t)(kk + ty) * 256 + n0 + tx * 4);
        *(float4*)&Ws[ty][tx * 4] = wv;
        __syncthreads();

        #pragma unroll
        for (int c = 0; c < 16; c++) {
            float a0 = As[ty*4+0][c];
            float a1 = As[ty*4+1][c];
            float a2 = As[ty*4+2][c];
            float a3 = As[ty*4+3][c];
            float4 w = *(const float4*)&Ws[c][tx * 4];
            acc[0][0] += a0*w.x; acc[0][1] += a0*w.y; acc[0][2] += a0*w.z; acc[0][3] += a0*w.w;
            acc[1][0] += a1*w.x; acc[1][1] += a1*w.y; acc[1][2] += a1*w.z; acc[1][3] += a1*w.w;
            acc[2][0] += a2*w.x; acc[2][1] += a2*w.y; acc[2][2] += a2*w.z; acc[2][3] += a2*w.w;
            acc[3][0] += a3*w.x; acc[3][1] += a3*w.y; acc[3][2] += a3*w.z; acc[3][3] += a3*w.w;
        }
        __syncthreads();
    }

    float4 bv = make_float4(0.f, 0.f, 0.f, 0.f);
    if (ADD_BIAS) bv = *(const float4*)(bias + n0 + tx * 4);
    #pragma unroll
    for (int j = 0; j < 4; j++) {
        float4 o = make_float4(acc[j][0] + bv.x, acc[j][1] + bv.y,
                               acc[j][2] + bv.z, acc[j][3] + bv.w);
        *(float4*)(C + (size_t)(m0 + ty*4 + j) * 256 + n0 + tx * 4) = o;
    }
}

// ---------------------------------------------------------------------------
// Attention: per q-row streaming (max, argmax, sumexp) over all 4096 keys,
// then out_row = p * V[argmax] if p >= 0.6 else 0. The attention matrix and
// attn@V GEMM are never materialized (softmax rows sum to 1, so at most one
// entry can be >= 0.6, and it must be the row max).
// ---------------------------------------------------------------------------
#define QPAD 260
#define KPAD 33
#define SMEM_ATTN ((size_t)(64*QPAD + 64*KPAD + 64) * sizeof(float) + 64 * sizeof(int))

__global__ __launch_bounds__(256) void attn_kernel(const float* __restrict__ Qg_,
                                                   const float* __restrict__ Kg_,
                                                   const float* __restrict__ Vg_,
                                                   float* __restrict__ Og_)
{
    extern __shared__ float sm[];
    float* Qs      = sm;                  // [64][QPAD]
    float* Ks      = Qs + 64 * QPAD;      // [64][KPAD]
    float* rowsum  = Ks + 64 * KPAD;      // [64]
    int*   rowarg  = (int*)(rowsum + 64); // [64]

    const int t  = threadIdx.x;
    const int tx = t & 15;
    const int ty = t >> 4;
    const int b  = blockIdx.y;
    const int q0 = blockIdx.x * 64;
    const float SCALE = 0.17677669529663689f;   // (256/8)^-0.5

    const float* Qg = Qg_ + (size_t)(b * NN + q0) * DD;
    const float* Kb = Kg_ + (size_t)b * NN * DD;

    // Load 64x256 Q tile (pre-scaled) into padded smem
    #pragma unroll
    for (int i = 0; i < 16; i++) {
        int f4 = t + i * 256;
        int r = f4 >> 6, c4 = f4 & 63;
        float4 v = *(const float4*)(Qg + r * DD + c4 * 4);
        float4 s = make_float4(v.x * SCALE, v.y * SCALE, v.z * SCALE, v.w * SCALE);
        *(float4*)&Qs[r * QPAD + c4 * 4] = s;
    }

    // Per-row online-softmax state (identical copies in all 16 lanes of a row group)
    float rm[4], rs[4];
    int   ra[4];
    #pragma unroll
    for (int j = 0; j < 4; j++) { rm[j] = -1e30f; rs[j] = 0.f; ra[j] = 0; }

    const int klr = t >> 2;
    const int klc = (t & 3) * 8;

    for (int mt = 0; mt < 64; mt++) {
        float acc[4][4] = {};
        const float* Kt = Kb + (size_t)(mt * 64) * DD;

        for (int kk = 0; kk < 256; kk += 32) {
            __syncthreads();   // protect Ks from readers of previous chunk
            {
                const float* src = Kt + (size_t)klr * DD + kk + klc;
                float4 v0 = *(const float4*)(src);
                float4 v1 = *(const float4*)(src + 4);
                float* dst = &Ks[klr * KPAD + klc];
                dst[0]=v0.x; dst[1]=v0.y; dst[2]=v0.z; dst[3]=v0.w;
                dst[4]=v1.x; dst[5]=v1.y; dst[6]=v1.z; dst[7]=v1.w;
            }
            __syncthreads();

            #pragma unroll
            for (int c = 0; c < 32; c++) {
                float a[4], bv[4];
                #pragma unroll
                for (int j = 0; j < 4; j++) a[j]  = Qs[(ty*4 + j) * QPAD + kk + c];
                #pragma unroll
                for (int i = 0; i < 4; i++) bv[i] = Ks[(tx*4 + i) * KPAD + c];
                #pragma unroll
                for (int j = 0; j < 4; j++)
                    #pragma unroll
                    for (int i = 0; i < 4; i++)
                        acc[j][i] += a[j] * bv[i];
            }
        }

        // Row reduction: each row's 64 scores live in 16 consecutive lanes
        #pragma unroll
        for (int j = 0; j < 4; j++) {
            float lm = acc[j][0];
            int   la = tx * 4;
            #pragma unroll
            for (int i = 1; i < 4; i++)
                if (acc[j][i] > lm) { lm = acc[j][i]; la = tx * 4 + i; }
            #pragma unroll
            for (int off = 8; off; off >>= 1) {
                float om = __shfl_xor_sync(0xffffffffu, lm, off);
                int   oa = __shfl_xor_sync(0xffffffffu, la, off);
                if (om > lm || (om == lm && oa < la)) { lm = om; la = oa; }
            }
            float ts = 0.f;
            #pragma unroll
            for (int i = 0; i < 4; i++) ts += __expf(acc[j][i] - lm);
            #pragma unroll
            for (int off = 8; off; off >>= 1)
                ts += __shfl_xor_sync(0xffffffffu, ts, off);

            if (lm > rm[j]) {
                rs[j] = rs[j] * __expf(rm[j] - lm) + ts;
                rm[j] = lm;
                ra[j] = mt * 64 + la;
            } else {
                rs[j] += ts * __expf(lm - rm[j]);
            }
        }
    }

    if (tx == 0) {
        #pragma unroll
        for (int j = 0; j < 4; j++) {
            rowsum[ty*4 + j] = rs[j];
            rowarg[ty*4 + j] = ra[j];
        }
    }
    __syncthreads();

    // Gather: out_row = p * V[argmax] if p >= 0.6 else 0
    const float* Vb = Vg_ + (size_t)b * NN * DD;
    float*       Og = Og_ + (size_t)(b * NN + q0) * DD;
    #pragma unroll
    for (int i = 0; i < 16; i++) {
        int f4 = t + i * 256;
        int r = f4 >> 6, c4 = f4 & 63;
        float p = 1.0f / rowsum[r];
        float4 o = make_float4(0.f, 0.f, 0.f, 0.f);
        if (p >= 0.6f) {
            float4 v = *(const float4*)(Vb + (size_t)rowarg[r] * DD + c4 * 4);
            o = make_float4(v.x * p, v.y * p, v.z * p, v.w * p);
        }
        *(float4*)(Og + r * DD + c4 * 4) = o;
    }
}

// ---------------------------------------------------------------------------
extern "C" void kernel_launch(void* const* d_in, const int* in_sizes, int n_in,
                              void* d_out, int out_size)
{
    const float* x  = (const float*)d_in[0];
    const float* y  = (const float*)d_in[1];
    const float* Wq = (const float*)d_in[2];
    const float* Wk = (const float*)d_in[3];
    const float* Wv = (const float*)d_in[4];
    const float* Wp = (const float*)d_in[5];
    const float* bp = (const float*)d_in[6];
    float* out = (float*)d_out;

    float *Q, *K, *V, *Att;
    cudaGetSymbolAddress((void**)&Q,   g_Q);
    cudaGetSymbolAddress((void**)&K,   g_K);
    cudaGetSymbolAddress((void**)&V,   g_V);
    cudaGetSymbolAddress((void**)&Att, g_att);

    cudaFuncSetAttribute(attn_kernel,
                         cudaFuncAttributeMaxDynamicSharedMemorySize,
                         (int)SMEM_ATTN);

    dim3 ggrid(MTOT / 64, DD / 64);
    gemm256<false><<<ggrid, 256>>>(x, Wq, nullptr, Q);
    gemm256<false><<<ggrid, 256>>>(y, Wk, nullptr, K);
    gemm256<false><<<ggrid, 256>>>(x, Wv, nullptr, V);

    attn_kernel<<<dim3(NN / 64, BB), 256, SMEM_ATTN>>>(Q, K, V, Att);

    gemm256<true><<<ggrid, 256>>>(Att, Wp, bp, out);
}